// round 10
// baseline (speedup 1.0000x reference)
#include <cuda_runtime.h>
#include <cstdint>
#include <math.h>

// ---------------- problem constants ----------------
#define MTOK 2048
#define KDIM 2048
#define NDIM 1408
#define NEXP 8
#define CAP  1024
#define RROWS 4096
#define ECAP  8192

// ---------------- tiling ----------------
#define BM 128
#define BN1 128              // mlp1: 128 cols of gate AND up
#define BN2 256              // mlp2: 256 cols
#define BKT 16
#define SPAD 20              // 80-byte row stride: LDSM row addresses hit all 32 banks
#define NTHR 256
#define TSTAGE (BM * SPAD)               // floats per 128-row stage (2560)
#define SMEM_BYTES (9 * TSTAGE * 4)      // 92160 (both kernels)

// ---------------- scratch ----------------
__device__ __align__(16) float g_act[(size_t)ECAP * NDIM];  // SwiGLU out (tf32-rounded); rows>=cnt stay 0
__device__ __align__(16) float g_dbuf[(size_t)ECAP * KDIM];
__device__ int g_cnt[NEXP];
__device__ int g_rowtok[ECAP];
__device__ int g_posmap[RROWS];

// ---------------- helpers ----------------
__device__ __forceinline__ float to_tf32(float x) {
    float r;
    asm("cvt.rna.tf32.f32 %0, %1;" : "=f"(r) : "f"(x));
    return r;
}
__device__ __forceinline__ float4 cvt4(float4 v) {
    v.x = to_tf32(v.x); v.y = to_tf32(v.y);
    v.z = to_tf32(v.z); v.w = to_tf32(v.w);
    return v;
}
__device__ __forceinline__ void mma8(float4& d, const uint32_t* a, const uint32_t* b) {
    asm volatile(
        "mma.sync.aligned.m16n8k8.row.col.f32.tf32.tf32.f32 "
        "{%0,%1,%2,%3}, {%4,%5,%6,%7}, {%8,%9}, {%0,%1,%2,%3};\n"
        : "+f"(d.x), "+f"(d.y), "+f"(d.z), "+f"(d.w)
        : "r"(a[0]), "r"(a[1]), "r"(a[2]), "r"(a[3]), "r"(b[0]), "r"(b[1]));
}
__device__ __forceinline__ void ldsm_x4(uint32_t* a, uint32_t addr) {
    asm volatile("ldmatrix.sync.aligned.m8n8.x4.shared.b16 {%0,%1,%2,%3}, [%4];"
                 : "=r"(a[0]), "=r"(a[1]), "=r"(a[2]), "=r"(a[3]) : "r"(addr));
}
__device__ __forceinline__ void ldsm_x2(uint32_t* b, uint32_t addr) {
    asm volatile("ldmatrix.sync.aligned.m8n8.x2.shared.b16 {%0,%1}, [%2];"
                 : "=r"(b[0]), "=r"(b[1]) : "r"(addr));
}

// ---------------- routing ----------------
__global__ void k_route(const int* __restrict__ idx) {
    __shared__ int sc[NEXP];
    const int tid = threadIdx.x;
    if (tid < NEXP) sc[tid] = 0;
    __syncthreads();
    for (int r = tid; r < RROWS; r += blockDim.x) {
        int e = idx[r];
        int slot = atomicAdd(&sc[e], 1);
        if (slot < CAP) {
            int p = e * CAP + slot;
            g_rowtok[p] = r >> 1;
            g_posmap[r] = p;
        } else {
            g_posmap[r] = e * CAP;
        }
    }
    __syncthreads();
    if (tid < NEXP) g_cnt[tid] = min(sc[tid], CAP);
}

__device__ __forceinline__ float actf(float g, float u) {
    g = fminf(g, 10.0f);
    u = fminf(fmaxf(u, -10.0f), 10.0f);
    float s = g / (1.0f + expf(-g));
    return to_tf32(s * u);
}

// ---------------------------------------------------------------------------
// k_mlp1: fused gate+up GEMM, CTA 128x128 (both outputs), 8 warps 2(M)x4(N),
// warp tile 64x32 per output. 3-stage smem ring + double register staging:
// LDG for chunk kt+3 issued at iter kt, STS'd at iter kt+2 (2 compute bodies
// of latency hiding). SwiGLU in registers -> g_act.
// ---------------------------------------------------------------------------
__global__ __launch_bounds__(NTHR, 1)
void k_mlp1(const float* __restrict__ H, const float* __restrict__ Wg,
            const float* __restrict__ Wu) {
    extern __shared__ __align__(16) float smem[];
    float* As  = smem;                // 3 stages
    float* Bgs = smem + 3 * TSTAGE;   // 3 stages
    float* Bus = smem + 6 * TSTAGE;   // 3 stages

    const int e    = blockIdx.z;
    const int cnt  = g_cnt[e];
    const int row0 = blockIdx.y * BM;
    if (row0 >= cnt) return;
    const int col0 = blockIdx.x * BN1;

    const int tid  = threadIdx.x;
    const int lane = tid & 31;
    const int warp = tid >> 5;
    const int wm   = warp >> 2;
    const int wn   = warp & 3;
    const int grp  = lane >> 2;
    const int tig  = lane & 3;

    const int ar0 = tid >> 2;            // 0..63
    const int ak  = (tid & 3) * 4;
    const int ar1 = ar0 + 64;

    const bool av0 = (row0 + ar0) < cnt;
    const bool av1 = (row0 + ar1) < cnt;
    int t0 = av0 ? g_rowtok[e * CAP + row0 + ar0] : 0;
    int t1 = av1 ? g_rowtok[e * CAP + row0 + ar1] : 0;
    const float* ap0 = H + (size_t)t0 * KDIM + ak;
    const float* ap1 = H + (size_t)t1 * KDIM + ak;
    const size_t wbo = (size_t)e * ((size_t)NDIM * KDIM);
    const float* bg0 = Wg + wbo + (size_t)(col0 + ar0) * KDIM + ak;
    const float* bg1 = Wg + wbo + (size_t)(col0 + ar1) * KDIM + ak;
    const float* bu0 = Wu + wbo + (size_t)(col0 + ar0) * KDIM + ak;
    const float* bu1 = Wu + wbo + (size_t)(col0 + ar1) * KDIM + ak;

    const uint32_t sA  = (uint32_t)__cvta_generic_to_shared(As);
    const uint32_t sBg = (uint32_t)__cvta_generic_to_shared(Bgs);
    const uint32_t sBu = (uint32_t)__cvta_generic_to_shared(Bus);
    const int alm = lane & 15, alh = lane >> 4;
    const int blm = lane & 7,  blh = (lane >> 3) & 1;
    const uint32_t aBase  = sA  + (((wm * 64 + alm) * SPAD + alh * 4) << 2);
    const uint32_t bgBase = sBg + (((wn * 32 + blm) * SPAD + blh * 4) << 2);
    const uint32_t buBase = sBu + (((wn * 32 + blm) * SPAD + blh * 4) << 2);

    // Loader STS offsets (element index within a stage)
    const int so0 = ar0 * SPAD + ak;
    const int so1 = ar1 * SPAD + ak;

    float4 accg[4][4], accu[4][4];
#pragma unroll
    for (int i = 0; i < 4; ++i)
#pragma unroll
        for (int j = 0; j < 4; ++j) {
            accg[i][j] = make_float4(0.f, 0.f, 0.f, 0.f);
            accu[i][j] = make_float4(0.f, 0.f, 0.f, 0.f);
        }

    // Double register staging: R[q][0..5] = {a0,a1,g0,g1,u0,u1}
    float4 R[2][6];

#define MLP1_LDG(q, ko)                                                      \
    do {                                                                     \
        R[q][0] = make_float4(0.f, 0.f, 0.f, 0.f); R[q][1] = R[q][0];        \
        if (av0) R[q][0] = *(const float4*)(ap0 + (ko));                     \
        if (av1) R[q][1] = *(const float4*)(ap1 + (ko));                     \
        R[q][2] = *(const float4*)(bg0 + (ko));                              \
        R[q][3] = *(const float4*)(bg1 + (ko));                              \
        R[q][4] = *(const float4*)(bu0 + (ko));                              \
        R[q][5] = *(const float4*)(bu1 + (ko));                              \
    } while (0)

#define MLP1_STS(q, st)                                                      \
    do {                                                                     \
        float* a_ = As  + (st) * TSTAGE;                                     \
        float* g_ = Bgs + (st) * TSTAGE;                                     \
        float* u_ = Bus + (st) * TSTAGE;                                     \
        *(float4*)&a_[so0] = cvt4(R[q][0]);                                  \
        *(float4*)&a_[so1] = cvt4(R[q][1]);                                  \
        *(float4*)&g_[so0] = cvt4(R[q][2]);                                  \
        *(float4*)&g_[so1] = cvt4(R[q][3]);                                  \
        *(float4*)&u_[so0] = cvt4(R[q][4]);                                  \
        *(float4*)&u_[so1] = cvt4(R[q][5]);                                  \
    } while (0)

    const int KT = KDIM / BKT;   // 128
    // Prologue: stage0 direct, stage1 -> R[1], stage2 -> R[0]
    MLP1_LDG(0, 0);  MLP1_STS(0, 0);
    MLP1_LDG(1, BKT);
    MLP1_LDG(0, 2 * BKT);

    int stW = 1;   // stage index to write = (kt+1)%3
    int stC = 0;   // stage index to compute = kt%3
#pragma unroll 1
    for (int kt = 0; kt < KT; ++kt) {
        const int q = (kt + 1) & 1;
        if (kt + 1 < KT) MLP1_STS(q, stW);
        if (kt + 3 < KT) MLP1_LDG(q, (kt + 3) * BKT);
        __syncthreads();

        const uint32_t aS  = aBase  + (uint32_t)stC * (TSTAGE * 4);
        const uint32_t bgS = bgBase + (uint32_t)stC * (TSTAGE * 4);
        const uint32_t buS = buBase + (uint32_t)stC * (TSTAGE * 4);
#pragma unroll
        for (int ks = 0; ks < BKT; ks += 8) {
            uint32_t af[4][4], bgf[4][2], buf_[4][2];
#pragma unroll
            for (int mt = 0; mt < 4; ++mt)
                ldsm_x4(af[mt], aS + (uint32_t)(mt * 16 * SPAD + ks) * 4);
#pragma unroll
            for (int nt = 0; nt < 4; ++nt) {
                ldsm_x2(bgf[nt], bgS + (uint32_t)(nt * 8 * SPAD + ks) * 4);
                ldsm_x2(buf_[nt], buS + (uint32_t)(nt * 8 * SPAD + ks) * 4);
            }
#pragma unroll
            for (int mt = 0; mt < 4; ++mt)
#pragma unroll
                for (int nt = 0; nt < 4; ++nt) {
                    mma8(accg[mt][nt], af[mt], bgf[nt]);
                    mma8(accu[mt][nt], af[mt], buf_[nt]);
                }
        }
        stC = (stC == 2) ? 0 : stC + 1;
        stW = (stW == 2) ? 0 : stW + 1;
    }
#undef MLP1_LDG
#undef MLP1_STS

    // SwiGLU epilogue straight from registers
#pragma unroll
    for (int mt = 0; mt < 4; ++mt) {
        const int r0 = row0 + wm * 64 + mt * 16 + grp;
        const int r1 = r0 + 8;
#pragma unroll
        for (int nt = 0; nt < 4; ++nt) {
            const int c = col0 + wn * 32 + nt * 8 + tig * 2;
            float4 g = accg[mt][nt];
            float4 u = accu[mt][nt];
            if (r0 < cnt)
                *(float2*)&g_act[(size_t)(e * CAP + r0) * NDIM + c] =
                    make_float2(actf(g.x, u.x), actf(g.y, u.y));
            if (r1 < cnt)
                *(float2*)&g_act[(size_t)(e * CAP + r1) * NDIM + c] =
                    make_float2(actf(g.z, u.z), actf(g.w, u.w));
        }
    }
}

// ---------------------------------------------------------------------------
// k_mlp2: down-projection, CTA 128x256, 8 warps 2(M)x4(N), warp tile 64x64.
// Same 3-stage ring + double register staging. A = g_act (pre-rounded).
// ---------------------------------------------------------------------------
__global__ __launch_bounds__(NTHR, 1)
void k_mlp2(const float* __restrict__ W) {
    extern __shared__ __align__(16) float smem[];
    float* As = smem;                 // 3 stages of 128 rows
    float* Bs = smem + 3 * TSTAGE;    // 3 stages of 256 rows

    const int e    = blockIdx.z;
    const int cnt  = g_cnt[e];
    const int row0 = blockIdx.y * BM;
    if (row0 >= cnt) return;
    const int col0 = blockIdx.x * BN2;

    const int tid  = threadIdx.x;
    const int lane = tid & 31;
    const int warp = tid >> 5;
    const int wm   = warp >> 2;
    const int wn   = warp & 3;
    const int grp  = lane >> 2;
    const int tig  = lane & 3;

    const int ar0 = tid >> 2;            // 0..63
    const int ak  = (tid & 3) * 4;
    const int ar1 = ar0 + 64;

    const float* ap0 = g_act + (size_t)(e * CAP + row0 + ar0) * NDIM + ak;
    const float* ap1 = g_act + (size_t)(e * CAP + row0 + ar1) * NDIM + ak;
    const size_t wbo = (size_t)e * ((size_t)NDIM * KDIM);
    const float* bp[4];
#pragma unroll
    for (int j = 0; j < 4; ++j)
        bp[j] = W + wbo + (size_t)(col0 + ar0 + j * 64) * NDIM + ak;

    const uint32_t sA = (uint32_t)__cvta_generic_to_shared(As);
    const uint32_t sB = (uint32_t)__cvta_generic_to_shared(Bs);
    const int alm = lane & 15, alh = lane >> 4;
    const int blm = lane & 7,  blh = (lane >> 3) & 1;
    const uint32_t aBase = sA + (((wm * 64 + alm) * SPAD + alh * 4) << 2);
    const uint32_t bBase = sB + (((wn * 64 + blm) * SPAD + blh * 4) << 2);

    const int so0 = ar0 * SPAD + ak;
    const int so1 = ar1 * SPAD + ak;

    float4 acc[4][8];
#pragma unroll
    for (int i = 0; i < 4; ++i)
#pragma unroll
        for (int j = 0; j < 8; ++j) acc[i][j] = make_float4(0.f, 0.f, 0.f, 0.f);

    float4 RA[2][2], RB[2][4];

#define MLP2_LDG(q, ko)                                                      \
    do {                                                                     \
        RA[q][0] = *(const float4*)(ap0 + (ko));                             \
        RA[q][1] = *(const float4*)(ap1 + (ko));                             \
        RB[q][0] = *(const float4*)(bp[0] + (ko));                           \
        RB[q][1] = *(const float4*)(bp[1] + (ko));                           \
        RB[q][2] = *(const float4*)(bp[2] + (ko));                           \
        RB[q][3] = *(const float4*)(bp[3] + (ko));                           \
    } while (0)

#define MLP2_STS(q, st)                                                      \
    do {                                                                     \
        float* a_ = As + (st) * TSTAGE;                                      \
        float* b_ = Bs + (st) * 2 * TSTAGE;                                  \
        *(float4*)&a_[so0] = RA[q][0];                                       \
        *(float4*)&a_[so1] = RA[q][1];                                       \
        *(float4*)&b_[so0] = cvt4(RB[q][0]);                                 \
        *(float4*)&b_[so0 + 64 * SPAD] = cvt4(RB[q][1]);                     \
        *(float4*)&b_[so0 + 128 * SPAD] = cvt4(RB[q][2]);                    \
        *(float4*)&b_[so0 + 192 * SPAD] = cvt4(RB[q][3]);                    \
    } while (0)

    const int KT = NDIM / BKT;   // 88
    MLP2_LDG(0, 0);  MLP2_STS(0, 0);
    MLP2_LDG(1, BKT);
    MLP2_LDG(0, 2 * BKT);

    int stW = 1;
    int stC = 0;
#pragma unroll 1
    for (int kt = 0; kt < KT; ++kt) {
        const int q = (kt + 1) & 1;
        if (kt + 1 < KT) MLP2_STS(q, stW);
        if (kt + 3 < KT) MLP2_LDG(q, (kt + 3) * BKT);
        __syncthreads();

        const uint32_t aS = aBase + (uint32_t)stC * (TSTAGE * 4);
        const uint32_t bS = bBase + (uint32_t)stC * (2 * TSTAGE * 4);
#pragma unroll
        for (int ks = 0; ks < BKT; ks += 8) {
            uint32_t af[4][4], bf[8][2];
#pragma unroll
            for (int mt = 0; mt < 4; ++mt)
                ldsm_x4(af[mt], aS + (uint32_t)(mt * 16 * SPAD + ks) * 4);
#pragma unroll
            for (int nt = 0; nt < 8; ++nt)
                ldsm_x2(bf[nt], bS + (uint32_t)(nt * 8 * SPAD + ks) * 4);
#pragma unroll
            for (int mt = 0; mt < 4; ++mt)
#pragma unroll
                for (int nt = 0; nt < 8; ++nt)
                    mma8(acc[mt][nt], af[mt], bf[nt]);
        }
        stC = (stC == 2) ? 0 : stC + 1;
        stW = (stW == 2) ? 0 : stW + 1;
    }
#undef MLP2_LDG
#undef MLP2_STS

#pragma unroll
    for (int mt = 0; mt < 4; ++mt) {
        const int r0 = row0 + wm * 64 + mt * 16 + grp;
        const int r1 = r0 + 8;
#pragma unroll
        for (int nt = 0; nt < 8; ++nt) {
            const int c = col0 + wn * 64 + nt * 8 + tig * 2;
            float4 v = acc[mt][nt];
            if (r0 < cnt) *(float2*)&g_dbuf[(size_t)(e * CAP + r0) * KDIM + c] = make_float2(v.x, v.y);
            if (r1 < cnt) *(float2*)&g_dbuf[(size_t)(e * CAP + r1) * KDIM + c] = make_float2(v.z, v.w);
        }
    }
}

// ---------------- combine ----------------
__global__ void k_combine(const float* __restrict__ gate, float* __restrict__ out) {
    const int t = blockIdx.x;
    const int p0 = g_posmap[2 * t];
    const int p1 = g_posmap[2 * t + 1];
    const float g0 = gate[2 * t];
    const float g1 = gate[2 * t + 1];
    const float4* d0 = (const float4*)(g_dbuf + (size_t)p0 * KDIM);
    const float4* d1 = (const float4*)(g_dbuf + (size_t)p1 * KDIM);
    float4* o = (float4*)(out + (size_t)t * KDIM);
    for (int i = threadIdx.x; i < KDIM / 4; i += blockDim.x) {
        float4 a = d0[i];
        float4 b = d1[i];
        o[i] = make_float4(g0 * a.x + g1 * b.x, g0 * a.y + g1 * b.y,
                           g0 * a.z + g1 * b.z, g0 * a.w + g1 * b.w);
    }
}

extern "C" void kernel_launch(void* const* d_in, const int* in_sizes, int n_in,
                              void* d_out, int out_size) {
    (void)in_sizes; (void)n_in; (void)out_size;
    const float* flat_h    = (const float*)d_in[0];
    const int*   flat_idx  = (const int*)  d_in[1];
    const float* flat_gate = (const float*)d_in[2];
    const float* gate_w    = (const float*)d_in[3];
    const float* up_w      = (const float*)d_in[4];
    const float* down_w    = (const float*)d_in[5];
    float* out = (float*)d_out;

    cudaFuncSetAttribute(k_mlp1, cudaFuncAttributeMaxDynamicSharedMemorySize, SMEM_BYTES);
    cudaFuncSetAttribute(k_mlp2, cudaFuncAttributeMaxDynamicSharedMemorySize, SMEM_BYTES);

    k_route<<<1, 256>>>(flat_idx);

    dim3 grid1(NDIM / BN1, CAP / BM, NEXP);   // (11, 8, 8)
    k_mlp1<<<grid1, NTHR, SMEM_BYTES>>>(flat_h, gate_w, up_w);

    dim3 grid2(KDIM / BN2, CAP / BM, NEXP);   // (8, 8, 8)
    k_mlp2<<<grid2, NTHR, SMEM_BYTES>>>(down_w);

    k_combine<<<MTOK, 256>>>(flat_gate, out);
}

// round 11
// speedup vs baseline: 2.4986x; 2.4986x over previous
#include <cuda_runtime.h>
#include <cstdint>
#include <math.h>

// ---------------- problem constants ----------------
#define MTOK 2048
#define KDIM 2048
#define NDIM 1408
#define NEXP 8
#define CAP  1024
#define RROWS 4096
#define ECAP  8192

// ---------------- tiling ----------------
#define BM 128
#define BN1 128              // mlp1: 128 cols of gate AND up
#define BN2 256              // mlp2: 256 cols
#define BKT 16
#define SPAD 20              // 80B row stride: LDSM row addresses hit all 32 banks
#define NTHR 256
#define NSTG 4               // cp.async ring stages
#define TSTAGE (BM * SPAD)   // floats per 128-row stage (2560)
#define SMEM_BYTES (12 * TSTAGE * 4)   // 122880 (both kernels)

// ---------------- scratch ----------------
__device__ __align__(16) float g_act[(size_t)ECAP * NDIM];  // SwiGLU out (tf32-rounded); rows>=cnt stay 0
__device__ __align__(16) float g_dbuf[(size_t)ECAP * KDIM];
__device__ int g_cnt[NEXP];
__device__ int g_rowtok[ECAP];
__device__ int g_posmap[RROWS];

// ---------------- helpers ----------------
__device__ __forceinline__ float to_tf32(float x) {
    float r;
    asm("cvt.rna.tf32.f32 %0, %1;" : "=f"(r) : "f"(x));
    return r;
}
__device__ __forceinline__ void mma8(float4& d, const uint32_t* a, const uint32_t* b) {
    asm volatile(
        "mma.sync.aligned.m16n8k8.row.col.f32.tf32.tf32.f32 "
        "{%0,%1,%2,%3}, {%4,%5,%6,%7}, {%8,%9}, {%0,%1,%2,%3};\n"
        : "+f"(d.x), "+f"(d.y), "+f"(d.z), "+f"(d.w)
        : "r"(a[0]), "r"(a[1]), "r"(a[2]), "r"(a[3]), "r"(b[0]), "r"(b[1]));
}
__device__ __forceinline__ void ldsm_x4(uint32_t* a, uint32_t addr) {
    asm volatile("ldmatrix.sync.aligned.m8n8.x4.shared.b16 {%0,%1,%2,%3}, [%4];"
                 : "=r"(a[0]), "=r"(a[1]), "=r"(a[2]), "=r"(a[3]) : "r"(addr));
}
__device__ __forceinline__ void ldsm_x2(uint32_t* b, uint32_t addr) {
    asm volatile("ldmatrix.sync.aligned.m8n8.x2.shared.b16 {%0,%1}, [%2];"
                 : "=r"(b[0]), "=r"(b[1]) : "r"(addr));
}
// tf32-round fragments in place (applied post-ldmatrix, pre-mma)
__device__ __forceinline__ void cvt_frag(uint32_t* f, int n) {
#pragma unroll
    for (int i = 0; i < n; ++i)
        f[i] = __float_as_uint(to_tf32(__uint_as_float(f[i])));
}
__device__ __forceinline__ void cp16(uint32_t saddr, const void* gptr, int srcbytes) {
    asm volatile("cp.async.ca.shared.global [%0], [%1], 16, %2;"
                 :: "r"(saddr), "l"(gptr), "r"(srcbytes));
}
#define CP_COMMIT() asm volatile("cp.async.commit_group;" ::: "memory")
#define CP_WAIT2()  asm volatile("cp.async.wait_group 2;" ::: "memory")

// ---------------- routing ----------------
__global__ void k_route(const int* __restrict__ idx) {
    __shared__ int sc[NEXP];
    const int tid = threadIdx.x;
    if (tid < NEXP) sc[tid] = 0;
    __syncthreads();
    for (int r = tid; r < RROWS; r += blockDim.x) {
        int e = idx[r];
        int slot = atomicAdd(&sc[e], 1);
        if (slot < CAP) {
            int p = e * CAP + slot;
            g_rowtok[p] = r >> 1;
            g_posmap[r] = p;
        } else {
            g_posmap[r] = e * CAP;
        }
    }
    __syncthreads();
    if (tid < NEXP) g_cnt[tid] = min(sc[tid], CAP);
}

__device__ __forceinline__ float actf(float g, float u) {
    g = fminf(g, 10.0f);
    u = fminf(fmaxf(u, -10.0f), 10.0f);
    float s = g / (1.0f + expf(-g));
    return to_tf32(s * u);
}

// ---------------------------------------------------------------------------
// k_mlp1: fused gate+up GEMM, CTA 128x128 (both outputs), 8 warps 2(M)x4(N),
// warp tile 64x32 per output. 4-stage cp.async ring, issue-ahead 2.
// tf32 rounding applied on fragments. SwiGLU in registers -> g_act.
// ---------------------------------------------------------------------------
__global__ __launch_bounds__(NTHR, 1)
void k_mlp1(const float* __restrict__ H, const float* __restrict__ Wg,
            const float* __restrict__ Wu) {
    extern __shared__ __align__(16) float smem[];
    float* As  = smem;                // 4 stages
    float* Bgs = smem + 4 * TSTAGE;   // 4 stages
    float* Bus = smem + 8 * TSTAGE;   // 4 stages

    const int e    = blockIdx.z;
    const int cnt  = g_cnt[e];
    const int row0 = blockIdx.y * BM;
    if (row0 >= cnt) return;
    const int col0 = blockIdx.x * BN1;

    const int tid  = threadIdx.x;
    const int lane = tid & 31;
    const int warp = tid >> 5;
    const int wm   = warp >> 2;
    const int wn   = warp & 3;
    const int grp  = lane >> 2;
    const int tig  = lane & 3;

    const int ar0 = tid >> 2;            // 0..63
    const int ak  = (tid & 3) * 4;
    const int ar1 = ar0 + 64;

    const bool av0 = (row0 + ar0) < cnt;
    const bool av1 = (row0 + ar1) < cnt;
    const int sz0 = av0 ? 16 : 0;
    const int sz1 = av1 ? 16 : 0;
    int t0 = av0 ? g_rowtok[e * CAP + row0 + ar0] : 0;
    int t1 = av1 ? g_rowtok[e * CAP + row0 + ar1] : 0;
    const float* ap0 = H + (size_t)t0 * KDIM + ak;
    const float* ap1 = H + (size_t)t1 * KDIM + ak;
    const size_t wbo = (size_t)e * ((size_t)NDIM * KDIM);
    const float* bg0 = Wg + wbo + (size_t)(col0 + ar0) * KDIM + ak;
    const float* bg1 = Wg + wbo + (size_t)(col0 + ar1) * KDIM + ak;
    const float* bu0 = Wu + wbo + (size_t)(col0 + ar0) * KDIM + ak;
    const float* bu1 = Wu + wbo + (size_t)(col0 + ar1) * KDIM + ak;

    const uint32_t sA  = (uint32_t)__cvta_generic_to_shared(As);
    const uint32_t sBg = (uint32_t)__cvta_generic_to_shared(Bgs);
    const uint32_t sBu = (uint32_t)__cvta_generic_to_shared(Bus);
    const int alm = lane & 15, alh = lane >> 4;
    const int blm = lane & 7,  blh = (lane >> 3) & 1;
    const uint32_t aBase  = sA  + (((wm * 64 + alm) * SPAD + alh * 4) << 2);
    const uint32_t bgBase = sBg + (((wn * 32 + blm) * SPAD + blh * 4) << 2);
    const uint32_t buBase = sBu + (((wn * 32 + blm) * SPAD + blh * 4) << 2);

    const uint32_t wo0 = (uint32_t)(ar0 * SPAD + ak) * 4;   // byte offset in stage
    const uint32_t wo1 = (uint32_t)(ar1 * SPAD + ak) * 4;

    float4 accg[4][4], accu[4][4];
#pragma unroll
    for (int i = 0; i < 4; ++i)
#pragma unroll
        for (int j = 0; j < 4; ++j) {
            accg[i][j] = make_float4(0.f, 0.f, 0.f, 0.f);
            accu[i][j] = make_float4(0.f, 0.f, 0.f, 0.f);
        }

#define MLP1_CP(st, ko)                                                      \
    do {                                                                     \
        const uint32_t sa = sA  + (uint32_t)(st) * (TSTAGE * 4);             \
        const uint32_t sg = sBg + (uint32_t)(st) * (TSTAGE * 4);             \
        const uint32_t su = sBu + (uint32_t)(st) * (TSTAGE * 4);             \
        cp16(sa + wo0, ap0 + (ko), sz0);                                     \
        cp16(sa + wo1, ap1 + (ko), sz1);                                     \
        cp16(sg + wo0, bg0 + (ko), 16);                                      \
        cp16(sg + wo1, bg1 + (ko), 16);                                      \
        cp16(su + wo0, bu0 + (ko), 16);                                      \
        cp16(su + wo1, bu1 + (ko), 16);                                      \
    } while (0)

    const int KT = KDIM / BKT;   // 128
    MLP1_CP(0, 0);       CP_COMMIT();
    MLP1_CP(1, BKT);     CP_COMMIT();

#pragma unroll 1
    for (int kt = 0; kt < KT; ++kt) {
        if (kt + 2 < KT) MLP1_CP((kt + 2) & 3, (kt + 2) * BKT);
        CP_COMMIT();
        CP_WAIT2();
        __syncthreads();

        const int stC = kt & 3;
        const uint32_t aS  = aBase  + (uint32_t)stC * (TSTAGE * 4);
        const uint32_t bgS = bgBase + (uint32_t)stC * (TSTAGE * 4);
        const uint32_t buS = buBase + (uint32_t)stC * (TSTAGE * 4);
#pragma unroll
        for (int ks = 0; ks < BKT; ks += 8) {
            uint32_t af[4][4], bgf[4][2], buf_[4][2];
#pragma unroll
            for (int mt = 0; mt < 4; ++mt) {
                ldsm_x4(af[mt], aS + (uint32_t)(mt * 16 * SPAD + ks) * 4);
                cvt_frag(af[mt], 4);
            }
#pragma unroll
            for (int nt = 0; nt < 4; ++nt) {
                ldsm_x2(bgf[nt], bgS + (uint32_t)(nt * 8 * SPAD + ks) * 4);
                ldsm_x2(buf_[nt], buS + (uint32_t)(nt * 8 * SPAD + ks) * 4);
                cvt_frag(bgf[nt], 2);
                cvt_frag(buf_[nt], 2);
            }
#pragma unroll
            for (int mt = 0; mt < 4; ++mt)
#pragma unroll
                for (int nt = 0; nt < 4; ++nt) {
                    mma8(accg[mt][nt], af[mt], bgf[nt]);
                    mma8(accu[mt][nt], af[mt], buf_[nt]);
                }
        }
    }
#undef MLP1_CP

    // SwiGLU epilogue straight from registers
#pragma unroll
    for (int mt = 0; mt < 4; ++mt) {
        const int r0 = row0 + wm * 64 + mt * 16 + grp;
        const int r1 = r0 + 8;
#pragma unroll
        for (int nt = 0; nt < 4; ++nt) {
            const int c = col0 + wn * 32 + nt * 8 + tig * 2;
            float4 g = accg[mt][nt];
            float4 u = accu[mt][nt];
            if (r0 < cnt)
                *(float2*)&g_act[(size_t)(e * CAP + r0) * NDIM + c] =
                    make_float2(actf(g.x, u.x), actf(g.y, u.y));
            if (r1 < cnt)
                *(float2*)&g_act[(size_t)(e * CAP + r1) * NDIM + c] =
                    make_float2(actf(g.z, u.z), actf(g.w, u.w));
        }
    }
}

// ---------------------------------------------------------------------------
// k_mlp2: down-projection, CTA 128x256, 8 warps 2(M)x4(N), warp tile 64x64.
// 4-stage cp.async ring. A = g_act (pre-rounded: no fragment cvt); B cvt'd
// on fragments.
// ---------------------------------------------------------------------------
__global__ __launch_bounds__(NTHR, 1)
void k_mlp2(const float* __restrict__ W) {
    extern __shared__ __align__(16) float smem[];
    float* As = smem;                 // 4 stages of 128 rows
    float* Bs = smem + 4 * TSTAGE;    // 4 stages of 256 rows

    const int e    = blockIdx.z;
    const int cnt  = g_cnt[e];
    const int row0 = blockIdx.y * BM;
    if (row0 >= cnt) return;
    const int col0 = blockIdx.x * BN2;

    const int tid  = threadIdx.x;
    const int lane = tid & 31;
    const int warp = tid >> 5;
    const int wm   = warp >> 2;
    const int wn   = warp & 3;
    const int grp  = lane >> 2;
    const int tig  = lane & 3;

    const int ar0 = tid >> 2;            // 0..63
    const int ak  = (tid & 3) * 4;
    const int ar1 = ar0 + 64;

    const float* ap0 = g_act + (size_t)(e * CAP + row0 + ar0) * NDIM + ak;
    const float* ap1 = g_act + (size_t)(e * CAP + row0 + ar1) * NDIM + ak;
    const size_t wbo = (size_t)e * ((size_t)NDIM * KDIM);
    const float* bp[4];
#pragma unroll
    for (int j = 0; j < 4; ++j)
        bp[j] = W + wbo + (size_t)(col0 + ar0 + j * 64) * NDIM + ak;

    const uint32_t sA = (uint32_t)__cvta_generic_to_shared(As);
    const uint32_t sB = (uint32_t)__cvta_generic_to_shared(Bs);
    const int alm = lane & 15, alh = lane >> 4;
    const int blm = lane & 7,  blh = (lane >> 3) & 1;
    const uint32_t aBase = sA + (((wm * 64 + alm) * SPAD + alh * 4) << 2);
    const uint32_t bBase = sB + (((wn * 64 + blm) * SPAD + blh * 4) << 2);

    const uint32_t wo0 = (uint32_t)(ar0 * SPAD + ak) * 4;
    const uint32_t wo1 = (uint32_t)(ar1 * SPAD + ak) * 4;

    float4 acc[4][8];
#pragma unroll
    for (int i = 0; i < 4; ++i)
#pragma unroll
        for (int j = 0; j < 8; ++j) acc[i][j] = make_float4(0.f, 0.f, 0.f, 0.f);

#define MLP2_CP(st, ko)                                                      \
    do {                                                                     \
        const uint32_t sa = sA + (uint32_t)(st) * (TSTAGE * 4);              \
        const uint32_t sb = sB + (uint32_t)(st) * (2 * TSTAGE * 4);          \
        cp16(sa + wo0, ap0 + (ko), 16);                                      \
        cp16(sa + wo1, ap1 + (ko), 16);                                      \
        cp16(sb + wo0,                       bp[0] + (ko), 16);              \
        cp16(sb + wo0 + 64 * SPAD * 4,       bp[1] + (ko), 16);              \
        cp16(sb + wo0 + 128 * SPAD * 4,      bp[2] + (ko), 16);              \
        cp16(sb + wo0 + 192 * SPAD * 4,      bp[3] + (ko), 16);              \
    } while (0)

    const int KT = NDIM / BKT;   // 88
    MLP2_CP(0, 0);     CP_COMMIT();
    MLP2_CP(1, BKT);   CP_COMMIT();

#pragma unroll 1
    for (int kt = 0; kt < KT; ++kt) {
        if (kt + 2 < KT) MLP2_CP((kt + 2) & 3, (kt + 2) * BKT);
        CP_COMMIT();
        CP_WAIT2();
        __syncthreads();

        const int stC = kt & 3;
        const uint32_t aS = aBase + (uint32_t)stC * (TSTAGE * 4);
        const uint32_t bS = bBase + (uint32_t)stC * (2 * TSTAGE * 4);
#pragma unroll
        for (int ks = 0; ks < BKT; ks += 8) {
            uint32_t af[4][4], bf[8][2];
#pragma unroll
            for (int mt = 0; mt < 4; ++mt)
                ldsm_x4(af[mt], aS + (uint32_t)(mt * 16 * SPAD + ks) * 4);
#pragma unroll
            for (int nt = 0; nt < 8; ++nt) {
                ldsm_x2(bf[nt], bS + (uint32_t)(nt * 8 * SPAD + ks) * 4);
                cvt_frag(bf[nt], 2);
            }
#pragma unroll
            for (int mt = 0; mt < 4; ++mt)
#pragma unroll
                for (int nt = 0; nt < 8; ++nt)
                    mma8(acc[mt][nt], af[mt], bf[nt]);
        }
    }
#undef MLP2_CP

#pragma unroll
    for (int mt = 0; mt < 4; ++mt) {
        const int r0 = row0 + wm * 64 + mt * 16 + grp;
        const int r1 = r0 + 8;
#pragma unroll
        for (int nt = 0; nt < 8; ++nt) {
            const int c = col0 + wn * 64 + nt * 8 + tig * 2;
            float4 v = acc[mt][nt];
            if (r0 < cnt) *(float2*)&g_dbuf[(size_t)(e * CAP + r0) * KDIM + c] = make_float2(v.x, v.y);
            if (r1 < cnt) *(float2*)&g_dbuf[(size_t)(e * CAP + r1) * KDIM + c] = make_float2(v.z, v.w);
        }
    }
}

// ---------------- combine ----------------
__global__ void k_combine(const float* __restrict__ gate, float* __restrict__ out) {
    const int t = blockIdx.x;
    const int p0 = g_posmap[2 * t];
    const int p1 = g_posmap[2 * t + 1];
    const float g0 = gate[2 * t];
    const float g1 = gate[2 * t + 1];
    const float4* d0 = (const float4*)(g_dbuf + (size_t)p0 * KDIM);
    const float4* d1 = (const float4*)(g_dbuf + (size_t)p1 * KDIM);
    float4* o = (float4*)(out + (size_t)t * KDIM);
    for (int i = threadIdx.x; i < KDIM / 4; i += blockDim.x) {
        float4 a = d0[i];
        float4 b = d1[i];
        o[i] = make_float4(g0 * a.x + g1 * b.x, g0 * a.y + g1 * b.y,
                           g0 * a.z + g1 * b.z, g0 * a.w + g1 * b.w);
    }
}

extern "C" void kernel_launch(void* const* d_in, const int* in_sizes, int n_in,
                              void* d_out, int out_size) {
    (void)in_sizes; (void)n_in; (void)out_size;
    const float* flat_h    = (const float*)d_in[0];
    const int*   flat_idx  = (const int*)  d_in[1];
    const float* flat_gate = (const float*)d_in[2];
    const float* gate_w    = (const float*)d_in[3];
    const float* up_w      = (const float*)d_in[4];
    const float* down_w    = (const float*)d_in[5];
    float* out = (float*)d_out;

    cudaFuncSetAttribute(k_mlp1, cudaFuncAttributeMaxDynamicSharedMemorySize, SMEM_BYTES);
    cudaFuncSetAttribute(k_mlp2, cudaFuncAttributeMaxDynamicSharedMemorySize, SMEM_BYTES);

    k_route<<<1, 256>>>(flat_idx);

    dim3 grid1(NDIM / BN1, CAP / BM, NEXP);   // (11, 8, 8)
    k_mlp1<<<grid1, NTHR, SMEM_BYTES>>>(flat_h, gate_w, up_w);

    dim3 grid2(KDIM / BN2, CAP / BM, NEXP);   // (8, 8, 8)
    k_mlp2<<<grid2, NTHR, SMEM_BYTES>>>(down_w);

    k_combine<<<MTOK, 256>>>(flat_gate, out);
}

// round 12
// speedup vs baseline: 3.6618x; 1.4656x over previous
#include <cuda_runtime.h>
#include <cuda_fp16.h>
#include <cstdint>
#include <math.h>

// ---------------- problem constants ----------------
#define MTOK 2048
#define KDIM 2048
#define NDIM 1408
#define NEXP 8
#define CAP  1024
#define RROWS 4096
#define ECAP  8192
#define WELEMS ((size_t)NEXP * NDIM * KDIM)   // 23,068,672

// ---------------- tiling ----------------
#define BM 128
#define BN1 128              // mlp1: 128 cols of gate AND up
#define BN2 256              // mlp2: 256 cols
#define BKT 32               // fp16 elems per k-chunk (64 B/row)
#define SPADH 40             // halves per row slot (80 B stride, conflict-free LDSM)
#define NTHR 256
#define NSTG 4
#define TSTH (BM * SPADH)    // 5120 halves per 128-row stage
#define SMEM_BYTES (12 * TSTH * 2)   // 122880 (both kernels)

// ---------------- scratch (device globals, allocation-free rule) ----------------
__device__ __align__(16) __half g_h16[(size_t)MTOK * KDIM];
__device__ __align__(16) __half g_wg16[WELEMS];
__device__ __align__(16) __half g_wu16[WELEMS];
__device__ __align__(16) __half g_wd16[WELEMS];
__device__ __align__(16) __half g_act16[(size_t)ECAP * NDIM];  // rows>=cnt stay 0
__device__ __align__(16) float  g_dbuf[(size_t)ECAP * KDIM];
__device__ int g_cnt[NEXP];
__device__ int g_rowtok[ECAP];
__device__ int g_posmap[RROWS];

// ---------------- helpers ----------------
__device__ __forceinline__ void mma16(float4& d, const uint32_t* a, const uint32_t* b) {
    asm volatile(
        "mma.sync.aligned.m16n8k16.row.col.f32.f16.f16.f32 "
        "{%0,%1,%2,%3}, {%4,%5,%6,%7}, {%8,%9}, {%0,%1,%2,%3};\n"
        : "+f"(d.x), "+f"(d.y), "+f"(d.z), "+f"(d.w)
        : "r"(a[0]), "r"(a[1]), "r"(a[2]), "r"(a[3]), "r"(b[0]), "r"(b[1]));
}
__device__ __forceinline__ void ldsm_x4(uint32_t* a, uint32_t addr) {
    asm volatile("ldmatrix.sync.aligned.m8n8.x4.shared.b16 {%0,%1,%2,%3}, [%4];"
                 : "=r"(a[0]), "=r"(a[1]), "=r"(a[2]), "=r"(a[3]) : "r"(addr));
}
__device__ __forceinline__ void ldsm_x2(uint32_t* b, uint32_t addr) {
    asm volatile("ldmatrix.sync.aligned.m8n8.x2.shared.b16 {%0,%1}, [%2];"
                 : "=r"(b[0]), "=r"(b[1]) : "r"(addr));
}
__device__ __forceinline__ void cp16(uint32_t saddr, const void* gptr, int srcbytes) {
    asm volatile("cp.async.ca.shared.global [%0], [%1], 16, %2;"
                 :: "r"(saddr), "l"(gptr), "r"(srcbytes));
}
#define CP_COMMIT() asm volatile("cp.async.commit_group;" ::: "memory")
#define CP_WAIT2()  asm volatile("cp.async.wait_group 2;" ::: "memory")

// ---------------- f32 -> fp16 conversion (streaming) ----------------
__global__ void k_cvt(const float* __restrict__ s, __half* __restrict__ d, int n) {
    int i = (blockIdx.x * blockDim.x + threadIdx.x) * 8;
    if (i >= n) return;
    float4 a = *(const float4*)(s + i);
    float4 b = *(const float4*)(s + i + 4);
    __half2 h[4];
    h[0] = __floats2half2_rn(a.x, a.y);
    h[1] = __floats2half2_rn(a.z, a.w);
    h[2] = __floats2half2_rn(b.x, b.y);
    h[3] = __floats2half2_rn(b.z, b.w);
    *(float4*)(d + i) = *(float4*)h;
}

// ---------------- routing ----------------
__global__ void k_route(const int* __restrict__ idx) {
    __shared__ int sc[NEXP];
    const int tid = threadIdx.x;
    if (tid < NEXP) sc[tid] = 0;
    __syncthreads();
    for (int r = tid; r < RROWS; r += blockDim.x) {
        int e = idx[r];
        int slot = atomicAdd(&sc[e], 1);
        if (slot < CAP) {
            int p = e * CAP + slot;
            g_rowtok[p] = r >> 1;
            g_posmap[r] = p;
        } else {
            g_posmap[r] = e * CAP;
        }
    }
    __syncthreads();
    if (tid < NEXP) g_cnt[tid] = min(sc[tid], CAP);
}

__device__ __forceinline__ float actf(float g, float u) {
    g = fminf(g, 10.0f);
    u = fminf(fmaxf(u, -10.0f), 10.0f);
    return (g / (1.0f + expf(-g))) * u;
}

// ---------------------------------------------------------------------------
// k_mlp1: fused gate+up fp16 GEMM, CTA 128x128 (both outputs), 8 warps
// 2(M)x4(N), warp tile 64x32 per output. 4-stage cp.async ring, issue-ahead 2.
// SwiGLU in registers -> g_act16 (fp16).
// ---------------------------------------------------------------------------
__global__ __launch_bounds__(NTHR, 1)
void k_mlp1() {
    extern __shared__ __align__(16) __half smem[];
    __half* As  = smem;                // 4 stages
    __half* Bgs = smem + 4 * TSTH;     // 4 stages
    __half* Bus = smem + 8 * TSTH;     // 4 stages

    const int e    = blockIdx.z;
    const int cnt  = g_cnt[e];
    const int row0 = blockIdx.y * BM;
    if (row0 >= cnt) return;
    const int col0 = blockIdx.x * BN1;

    const int tid  = threadIdx.x;
    const int lane = tid & 31;
    const int warp = tid >> 5;
    const int wm   = warp >> 2;
    const int wn   = warp & 3;
    const int grp  = lane >> 2;
    const int tig  = lane & 3;

    // Loader: thread -> (row = tid>>1, 32B half-row segment = (tid&1)*16 halves)
    const int lrow = tid >> 1;
    const int lseg = (tid & 1) * 16;

    const bool av = (row0 + lrow) < cnt;
    const int szA = av ? 16 : 0;
    int tok = av ? g_rowtok[e * CAP + row0 + lrow] : 0;
    const __half* ap = g_h16 + (size_t)tok * KDIM + lseg;
    const size_t wbo = (size_t)e * ((size_t)NDIM * KDIM);
    const __half* bg = g_wg16 + wbo + (size_t)(col0 + lrow) * KDIM + lseg;
    const __half* bu = g_wu16 + wbo + (size_t)(col0 + lrow) * KDIM + lseg;

    const uint32_t sA  = (uint32_t)__cvta_generic_to_shared(As);
    const uint32_t sBg = (uint32_t)__cvta_generic_to_shared(Bgs);
    const uint32_t sBu = (uint32_t)__cvta_generic_to_shared(Bus);
    const int alm = lane & 15, alh = lane >> 4;       // A: 16 rows x k-half(8)
    const int blm = lane & 7,  blh = (lane >> 3) & 1; // B: 8 rows x k-half (lanes 0-15)
    const uint32_t aBase  = sA  + (uint32_t)((wm * 64 + alm) * SPADH + alh * 8) * 2;
    const uint32_t bgBase = sBg + (uint32_t)((wn * 32 + blm) * SPADH + blh * 8) * 2;
    const uint32_t buBase = sBu + (uint32_t)((wn * 32 + blm) * SPADH + blh * 8) * 2;

    const uint32_t wof = (uint32_t)(lrow * SPADH + lseg) * 2;   // byte offset in stage

    float4 accg[4][4], accu[4][4];
#pragma unroll
    for (int i = 0; i < 4; ++i)
#pragma unroll
        for (int j = 0; j < 4; ++j) {
            accg[i][j] = make_float4(0.f, 0.f, 0.f, 0.f);
            accu[i][j] = make_float4(0.f, 0.f, 0.f, 0.f);
        }

#define MLP1_CP(st, ko)                                                      \
    do {                                                                     \
        const uint32_t sa = sA  + (uint32_t)(st) * (TSTH * 2) + wof;         \
        const uint32_t sg = sBg + (uint32_t)(st) * (TSTH * 2) + wof;         \
        const uint32_t su = sBu + (uint32_t)(st) * (TSTH * 2) + wof;         \
        cp16(sa,      ap + (ko),     szA);                                   \
        cp16(sa + 16, ap + (ko) + 8, szA);                                   \
        cp16(sg,      bg + (ko),     16);                                    \
        cp16(sg + 16, bg + (ko) + 8, 16);                                    \
        cp16(su,      bu + (ko),     16);                                    \
        cp16(su + 16, bu + (ko) + 8, 16);                                    \
    } while (0)

    const int KT = KDIM / BKT;   // 64
    MLP1_CP(0, 0);     CP_COMMIT();
    MLP1_CP(1, BKT);   CP_COMMIT();

#pragma unroll 1
    for (int kt = 0; kt < KT; ++kt) {
        if (kt + 2 < KT) MLP1_CP((kt + 2) & 3, (kt + 2) * BKT);
        CP_COMMIT();
        CP_WAIT2();
        __syncthreads();

        const int stC = kt & 3;
        const uint32_t aS  = aBase  + (uint32_t)stC * (TSTH * 2);
        const uint32_t bgS = bgBase + (uint32_t)stC * (TSTH * 2);
        const uint32_t buS = buBase + (uint32_t)stC * (TSTH * 2);
#pragma unroll
        for (int ks = 0; ks < BKT; ks += 16) {
            uint32_t af[4][4], bgf[4][2], buf_[4][2];
#pragma unroll
            for (int mt = 0; mt < 4; ++mt)
                ldsm_x4(af[mt], aS + (uint32_t)(mt * 16 * SPADH + ks) * 2);
#pragma unroll
            for (int nt = 0; nt < 4; ++nt) {
                ldsm_x2(bgf[nt], bgS + (uint32_t)(nt * 8 * SPADH + ks) * 2);
                ldsm_x2(buf_[nt], buS + (uint32_t)(nt * 8 * SPADH + ks) * 2);
            }
#pragma unroll
            for (int mt = 0; mt < 4; ++mt)
#pragma unroll
                for (int nt = 0; nt < 4; ++nt) {
                    mma16(accg[mt][nt], af[mt], bgf[nt]);
                    mma16(accu[mt][nt], af[mt], buf_[nt]);
                }
        }
    }
#undef MLP1_CP

    // SwiGLU epilogue -> g_act16 (fp16)
#pragma unroll
    for (int mt = 0; mt < 4; ++mt) {
        const int r0 = row0 + wm * 64 + mt * 16 + grp;
        const int r1 = r0 + 8;
#pragma unroll
        for (int nt = 0; nt < 4; ++nt) {
            const int c = col0 + wn * 32 + nt * 8 + tig * 2;
            float4 g = accg[mt][nt];
            float4 u = accu[mt][nt];
            if (r0 < cnt)
                *(__half2*)&g_act16[(size_t)(e * CAP + r0) * NDIM + c] =
                    __floats2half2_rn(actf(g.x, u.x), actf(g.y, u.y));
            if (r1 < cnt)
                *(__half2*)&g_act16[(size_t)(e * CAP + r1) * NDIM + c] =
                    __floats2half2_rn(actf(g.z, u.z), actf(g.w, u.w));
        }
    }
}

// ---------------------------------------------------------------------------
// k_mlp2: down-projection fp16 GEMM, CTA 128x256, 8 warps 2(M)x4(N), warp
// tile 64x64. A = g_act16 (rows>=cnt zero), B = g_wd16.
// ---------------------------------------------------------------------------
__global__ __launch_bounds__(NTHR, 1)
void k_mlp2() {
    extern __shared__ __align__(16) __half smem[];
    __half* As = smem;                 // 4 stages of 128 rows
    __half* Bs = smem + 4 * TSTH;      // 4 stages of 256 rows

    const int e    = blockIdx.z;
    const int cnt  = g_cnt[e];
    const int row0 = blockIdx.y * BM;
    if (row0 >= cnt) return;
    const int col0 = blockIdx.x * BN2;

    const int tid  = threadIdx.x;
    const int lane = tid & 31;
    const int warp = tid >> 5;
    const int wm   = warp >> 2;
    const int wn   = warp & 3;
    const int grp  = lane >> 2;
    const int tig  = lane & 3;

    const int lrow = tid >> 1;
    const int lseg = (tid & 1) * 16;

    const __half* ap = g_act16 + (size_t)(e * CAP + row0 + lrow) * NDIM + lseg;
    const size_t wbo = (size_t)e * ((size_t)NDIM * KDIM);
    const __half* bp0 = g_wd16 + wbo + (size_t)(col0 + lrow) * NDIM + lseg;
    const __half* bp1 = g_wd16 + wbo + (size_t)(col0 + lrow + 128) * NDIM + lseg;

    const uint32_t sA = (uint32_t)__cvta_generic_to_shared(As);
    const uint32_t sB = (uint32_t)__cvta_generic_to_shared(Bs);
    const int alm = lane & 15, alh = lane >> 4;
    const int blm = lane & 7,  blh = (lane >> 3) & 1;
    const uint32_t aBase = sA + (uint32_t)((wm * 64 + alm) * SPADH + alh * 8) * 2;
    const uint32_t bBase = sB + (uint32_t)((wn * 64 + blm) * SPADH + blh * 8) * 2;

    const uint32_t wofA = (uint32_t)(lrow * SPADH + lseg) * 2;
    const uint32_t wofB0 = wofA;
    const uint32_t wofB1 = (uint32_t)((lrow + 128) * SPADH + lseg) * 2;

    float4 acc[4][8];
#pragma unroll
    for (int i = 0; i < 4; ++i)
#pragma unroll
        for (int j = 0; j < 8; ++j) acc[i][j] = make_float4(0.f, 0.f, 0.f, 0.f);

#define MLP2_CP(st, ko)                                                      \
    do {                                                                     \
        const uint32_t sa = sA + (uint32_t)(st) * (TSTH * 2);                \
        const uint32_t sb = sB + (uint32_t)(st) * (2 * TSTH * 2);            \
        cp16(sa + wofA,       ap  + (ko),     16);                           \
        cp16(sa + wofA + 16,  ap  + (ko) + 8, 16);                           \
        cp16(sb + wofB0,      bp0 + (ko),     16);                           \
        cp16(sb + wofB0 + 16, bp0 + (ko) + 8, 16);                           \
        cp16(sb + wofB1,      bp1 + (ko),     16);                           \
        cp16(sb + wofB1 + 16, bp1 + (ko) + 8, 16);                           \
    } while (0)

    const int KT = NDIM / BKT;   // 44
    MLP2_CP(0, 0);     CP_COMMIT();
    MLP2_CP(1, BKT);   CP_COMMIT();

#pragma unroll 1
    for (int kt = 0; kt < KT; ++kt) {
        if (kt + 2 < KT) MLP2_CP((kt + 2) & 3, (kt + 2) * BKT);
        CP_COMMIT();
        CP_WAIT2();
        __syncthreads();

        const int stC = kt & 3;
        const uint32_t aS = aBase + (uint32_t)stC * (TSTH * 2);
        const uint32_t bS = bBase + (uint32_t)stC * (2 * TSTH * 2);
#pragma unroll
        for (int ks = 0; ks < BKT; ks += 16) {
            uint32_t af[4][4], bf[8][2];
#pragma unroll
            for (int mt = 0; mt < 4; ++mt)
                ldsm_x4(af[mt], aS + (uint32_t)(mt * 16 * SPADH + ks) * 2);
#pragma unroll
            for (int nt = 0; nt < 8; ++nt)
                ldsm_x2(bf[nt], bS + (uint32_t)(nt * 8 * SPADH + ks) * 2);
#pragma unroll
            for (int mt = 0; mt < 4; ++mt)
#pragma unroll
                for (int nt = 0; nt < 8; ++nt)
                    mma16(acc[mt][nt], af[mt], bf[nt]);
        }
    }
#undef MLP2_CP

#pragma unroll
    for (int mt = 0; mt < 4; ++mt) {
        const int r0 = row0 + wm * 64 + mt * 16 + grp;
        const int r1 = r0 + 8;
#pragma unroll
        for (int nt = 0; nt < 8; ++nt) {
            const int c = col0 + wn * 64 + nt * 8 + tig * 2;
            float4 v = acc[mt][nt];
            if (r0 < cnt) *(float2*)&g_dbuf[(size_t)(e * CAP + r0) * KDIM + c] = make_float2(v.x, v.y);
            if (r1 < cnt) *(float2*)&g_dbuf[(size_t)(e * CAP + r1) * KDIM + c] = make_float2(v.z, v.w);
        }
    }
}

// ---------------- combine ----------------
__global__ void k_combine(const float* __restrict__ gate, float* __restrict__ out) {
    const int t = blockIdx.x;
    const int p0 = g_posmap[2 * t];
    const int p1 = g_posmap[2 * t + 1];
    const float g0 = gate[2 * t];
    const float g1 = gate[2 * t + 1];
    const float4* d0 = (const float4*)(g_dbuf + (size_t)p0 * KDIM);
    const float4* d1 = (const float4*)(g_dbuf + (size_t)p1 * KDIM);
    float4* o = (float4*)(out + (size_t)t * KDIM);
    for (int i = threadIdx.x; i < KDIM / 4; i += blockDim.x) {
        float4 a = d0[i];
        float4 b = d1[i];
        o[i] = make_float4(g0 * a.x + g1 * b.x, g0 * a.y + g1 * b.y,
                           g0 * a.z + g1 * b.z, g0 * a.w + g1 * b.w);
    }
}

extern "C" void kernel_launch(void* const* d_in, const int* in_sizes, int n_in,
                              void* d_out, int out_size) {
    (void)in_sizes; (void)n_in; (void)out_size;
    const float* flat_h    = (const float*)d_in[0];
    const int*   flat_idx  = (const int*)  d_in[1];
    const float* flat_gate = (const float*)d_in[2];
    const float* gate_w    = (const float*)d_in[3];
    const float* up_w      = (const float*)d_in[4];
    const float* down_w    = (const float*)d_in[5];
    float* out = (float*)d_out;

    cudaFuncSetAttribute(k_mlp1, cudaFuncAttributeMaxDynamicSharedMemorySize, SMEM_BYTES);
    cudaFuncSetAttribute(k_mlp2, cudaFuncAttributeMaxDynamicSharedMemorySize, SMEM_BYTES);

    __half* d_h16;  cudaGetSymbolAddress((void**)&d_h16,  g_h16);
    __half* d_wg16; cudaGetSymbolAddress((void**)&d_wg16, g_wg16);
    __half* d_wu16; cudaGetSymbolAddress((void**)&d_wu16, g_wu16);
    __half* d_wd16; cudaGetSymbolAddress((void**)&d_wd16, g_wd16);

    const int HN = MTOK * KDIM;         // 4,194,304
    const int WN = (int)WELEMS;         // 23,068,672
    k_cvt<<<HN / 2048, 256>>>(flat_h, d_h16, HN);
    k_cvt<<<WN / 2048, 256>>>(gate_w, d_wg16, WN);
    k_cvt<<<WN / 2048, 256>>>(up_w,   d_wu16, WN);
    k_cvt<<<WN / 2048, 256>>>(down_w, d_wd16, WN);

    k_route<<<1, 256>>>(flat_idx);

    dim3 grid1(NDIM / BN1, CAP / BM, NEXP);   // (11, 8, 8)
    k_mlp1<<<grid1, NTHR, SMEM_BYTES>>>();

    dim3 grid2(KDIM / BN2, CAP / BM, NEXP);   // (8, 8, 8)
    k_mlp2<<<grid2, NTHR, SMEM_BYTES>>>();

    k_combine<<<MTOK, 256>>>(flat_gate, out);
}

// round 13
// speedup vs baseline: 3.6641x; 1.0006x over previous
#include <cuda_runtime.h>
#include <cuda_fp16.h>
#include <cstdint>
#include <math.h>

// ---------------- problem constants ----------------
#define MTOK 2048
#define KDIM 2048
#define NDIM 1408
#define NEXP 8
#define CAP  1024
#define RROWS 4096
#define ECAP  8192
#define WELEMS ((size_t)NEXP * NDIM * KDIM)   // 23,068,672

// ---------------- tiling ----------------
#define BM 128
#define BN1 128              // mlp1: 128 cols of gate AND up
#define BN2 256              // mlp2: 256 cols
#define BKT 32               // fp16 elems per k-chunk (64 B/row)
#define SPADH 40             // halves per row slot (80 B stride, conflict-free LDSM)
#define NTHR 256
#define NSTG 4
#define TSTH (BM * SPADH)    // 5120 halves per 128-row stage
#define SMEM_BYTES (12 * TSTH * 2)   // 122880 (both kernels)

// ---------------- scratch (device globals, allocation-free rule) ----------------
__device__ __align__(16) __half g_h16[(size_t)MTOK * KDIM];
__device__ __align__(16) __half g_wg16[WELEMS];
__device__ __align__(16) __half g_wu16[WELEMS];
__device__ __align__(16) __half g_wd16[WELEMS];
__device__ __align__(16) __half g_act16[(size_t)ECAP * NDIM];  // rows>=cnt stay 0
__device__ __align__(16) __half g_dbuf16[(size_t)ECAP * KDIM];
__device__ int g_cnt[NEXP];
__device__ int g_rowtok[ECAP];
__device__ int g_posmap[RROWS];

// ---------------- helpers ----------------
__device__ __forceinline__ void mma16(float4& d, const uint32_t* a, const uint32_t* b) {
    asm volatile(
        "mma.sync.aligned.m16n8k16.row.col.f32.f16.f16.f32 "
        "{%0,%1,%2,%3}, {%4,%5,%6,%7}, {%8,%9}, {%0,%1,%2,%3};\n"
        : "+f"(d.x), "+f"(d.y), "+f"(d.z), "+f"(d.w)
        : "r"(a[0]), "r"(a[1]), "r"(a[2]), "r"(a[3]), "r"(b[0]), "r"(b[1]));
}
__device__ __forceinline__ void ldsm_x4(uint32_t* a, uint32_t addr) {
    asm volatile("ldmatrix.sync.aligned.m8n8.x4.shared.b16 {%0,%1,%2,%3}, [%4];"
                 : "=r"(a[0]), "=r"(a[1]), "=r"(a[2]), "=r"(a[3]) : "r"(addr));
}
__device__ __forceinline__ void ldsm_x2(uint32_t* b, uint32_t addr) {
    asm volatile("ldmatrix.sync.aligned.m8n8.x2.shared.b16 {%0,%1}, [%2];"
                 : "=r"(b[0]), "=r"(b[1]) : "r"(addr));
}
__device__ __forceinline__ void cp16(uint32_t saddr, const void* gptr, int srcbytes) {
    asm volatile("cp.async.ca.shared.global [%0], [%1], 16, %2;"
                 :: "r"(saddr), "l"(gptr), "r"(srcbytes));
}
#define CP_COMMIT() asm volatile("cp.async.commit_group;" ::: "memory")
#define CP_WAIT2()  asm volatile("cp.async.wait_group 2;" ::: "memory")

// ---------------- f32 -> fp16 conversion (streaming, 16 elems/thread) ----------------
__global__ void k_cvt(const float* __restrict__ s, __half* __restrict__ d, int n) {
    int i = (blockIdx.x * blockDim.x + threadIdx.x) * 16;
    if (i >= n) return;
    float4 a = *(const float4*)(s + i);
    float4 b = *(const float4*)(s + i + 4);
    float4 c = *(const float4*)(s + i + 8);
    float4 e = *(const float4*)(s + i + 12);
    __half2 h0[4], h1[4];
    h0[0] = __floats2half2_rn(a.x, a.y);
    h0[1] = __floats2half2_rn(a.z, a.w);
    h0[2] = __floats2half2_rn(b.x, b.y);
    h0[3] = __floats2half2_rn(b.z, b.w);
    h1[0] = __floats2half2_rn(c.x, c.y);
    h1[1] = __floats2half2_rn(c.z, c.w);
    h1[2] = __floats2half2_rn(e.x, e.y);
    h1[3] = __floats2half2_rn(e.z, e.w);
    *(float4*)(d + i)     = *(float4*)h0;
    *(float4*)(d + i + 8) = *(float4*)h1;
}

// ---------------- routing ----------------
__global__ void k_route(const int* __restrict__ idx) {
    __shared__ int sc[NEXP];
    const int tid = threadIdx.x;
    if (tid < NEXP) sc[tid] = 0;
    __syncthreads();
    for (int r = tid; r < RROWS; r += blockDim.x) {
        int e = idx[r];
        int slot = atomicAdd(&sc[e], 1);
        if (slot < CAP) {
            int p = e * CAP + slot;
            g_rowtok[p] = r >> 1;
            g_posmap[r] = p;
        } else {
            g_posmap[r] = e * CAP;
        }
    }
    __syncthreads();
    if (tid < NEXP) g_cnt[tid] = min(sc[tid], CAP);
}

__device__ __forceinline__ float actf(float g, float u) {
    g = fminf(g, 10.0f);
    u = fminf(fmaxf(u, -10.0f), 10.0f);
    return (g / (1.0f + expf(-g))) * u;
}

// ---------------------------------------------------------------------------
// k_mlp1: fused gate+up fp16 GEMM, CTA 128x128 (both outputs), 8 warps
// 2(M)x4(N), warp tile 64x32 per output. 4-stage cp.async ring, issue-ahead 2.
// SwiGLU in registers -> g_act16 (fp16).
// ---------------------------------------------------------------------------
__global__ __launch_bounds__(NTHR, 1)
void k_mlp1() {
    extern __shared__ __align__(16) __half smem[];
    __half* As  = smem;                // 4 stages
    __half* Bgs = smem + 4 * TSTH;     // 4 stages
    __half* Bus = smem + 8 * TSTH;     // 4 stages

    const int e    = blockIdx.z;
    const int cnt  = g_cnt[e];
    const int row0 = blockIdx.y * BM;
    if (row0 >= cnt) return;
    const int col0 = blockIdx.x * BN1;

    const int tid  = threadIdx.x;
    const int lane = tid & 31;
    const int warp = tid >> 5;
    const int wm   = warp >> 2;
    const int wn   = warp & 3;
    const int grp  = lane >> 2;
    const int tig  = lane & 3;

    const int lrow = tid >> 1;
    const int lseg = (tid & 1) * 16;

    const bool av = (row0 + lrow) < cnt;
    const int szA = av ? 16 : 0;
    int tok = av ? g_rowtok[e * CAP + row0 + lrow] : 0;
    const __half* ap = g_h16 + (size_t)tok * KDIM + lseg;
    const size_t wbo = (size_t)e * ((size_t)NDIM * KDIM);
    const __half* bg = g_wg16 + wbo + (size_t)(col0 + lrow) * KDIM + lseg;
    const __half* bu = g_wu16 + wbo + (size_t)(col0 + lrow) * KDIM + lseg;

    const uint32_t sA  = (uint32_t)__cvta_generic_to_shared(As);
    const uint32_t sBg = (uint32_t)__cvta_generic_to_shared(Bgs);
    const uint32_t sBu = (uint32_t)__cvta_generic_to_shared(Bus);
    const int alm = lane & 15, alh = lane >> 4;
    const int blm = lane & 7,  blh = (lane >> 3) & 1;
    const uint32_t aBase  = sA  + (uint32_t)((wm * 64 + alm) * SPADH + alh * 8) * 2;
    const uint32_t bgBase = sBg + (uint32_t)((wn * 32 + blm) * SPADH + blh * 8) * 2;
    const uint32_t buBase = sBu + (uint32_t)((wn * 32 + blm) * SPADH + blh * 8) * 2;

    const uint32_t wof = (uint32_t)(lrow * SPADH + lseg) * 2;

    float4 accg[4][4], accu[4][4];
#pragma unroll
    for (int i = 0; i < 4; ++i)
#pragma unroll
        for (int j = 0; j < 4; ++j) {
            accg[i][j] = make_float4(0.f, 0.f, 0.f, 0.f);
            accu[i][j] = make_float4(0.f, 0.f, 0.f, 0.f);
        }

#define MLP1_CP(st, ko)                                                      \
    do {                                                                     \
        const uint32_t sa = sA  + (uint32_t)(st) * (TSTH * 2) + wof;         \
        const uint32_t sg = sBg + (uint32_t)(st) * (TSTH * 2) + wof;         \
        const uint32_t su = sBu + (uint32_t)(st) * (TSTH * 2) + wof;         \
        cp16(sa,      ap + (ko),     szA);                                   \
        cp16(sa + 16, ap + (ko) + 8, szA);                                   \
        cp16(sg,      bg + (ko),     16);                                    \
        cp16(sg + 16, bg + (ko) + 8, 16);                                    \
        cp16(su,      bu + (ko),     16);                                    \
        cp16(su + 16, bu + (ko) + 8, 16);                                    \
    } while (0)

    const int KT = KDIM / BKT;   // 64
    MLP1_CP(0, 0);     CP_COMMIT();
    MLP1_CP(1, BKT);   CP_COMMIT();

#pragma unroll 1
    for (int kt = 0; kt < KT; ++kt) {
        if (kt + 2 < KT) MLP1_CP((kt + 2) & 3, (kt + 2) * BKT);
        CP_COMMIT();
        CP_WAIT2();
        __syncthreads();

        const int stC = kt & 3;
        const uint32_t aS  = aBase  + (uint32_t)stC * (TSTH * 2);
        const uint32_t bgS = bgBase + (uint32_t)stC * (TSTH * 2);
        const uint32_t buS = buBase + (uint32_t)stC * (TSTH * 2);
#pragma unroll
        for (int ks = 0; ks < BKT; ks += 16) {
            uint32_t af[4][4], bgf[4][2], buf_[4][2];
#pragma unroll
            for (int mt = 0; mt < 4; ++mt)
                ldsm_x4(af[mt], aS + (uint32_t)(mt * 16 * SPADH + ks) * 2);
#pragma unroll
            for (int nt = 0; nt < 4; ++nt) {
                ldsm_x2(bgf[nt], bgS + (uint32_t)(nt * 8 * SPADH + ks) * 2);
                ldsm_x2(buf_[nt], buS + (uint32_t)(nt * 8 * SPADH + ks) * 2);
            }
#pragma unroll
            for (int mt = 0; mt < 4; ++mt)
#pragma unroll
                for (int nt = 0; nt < 4; ++nt) {
                    mma16(accg[mt][nt], af[mt], bgf[nt]);
                    mma16(accu[mt][nt], af[mt], buf_[nt]);
                }
        }
    }
#undef MLP1_CP

    // SwiGLU epilogue -> g_act16 (fp16)
#pragma unroll
    for (int mt = 0; mt < 4; ++mt) {
        const int r0 = row0 + wm * 64 + mt * 16 + grp;
        const int r1 = r0 + 8;
#pragma unroll
        for (int nt = 0; nt < 4; ++nt) {
            const int c = col0 + wn * 32 + nt * 8 + tig * 2;
            float4 g = accg[mt][nt];
            float4 u = accu[mt][nt];
            if (r0 < cnt)
                *(__half2*)&g_act16[(size_t)(e * CAP + r0) * NDIM + c] =
                    __floats2half2_rn(actf(g.x, u.x), actf(g.y, u.y));
            if (r1 < cnt)
                *(__half2*)&g_act16[(size_t)(e * CAP + r1) * NDIM + c] =
                    __floats2half2_rn(actf(g.z, u.z), actf(g.w, u.w));
        }
    }
}

// ---------------------------------------------------------------------------
// k_mlp2: down-projection fp16 GEMM, CTA 128x256, 8 warps 2(M)x4(N), warp
// tile 64x64. A = g_act16 (rows>=cnt zero), B = g_wd16. Output -> g_dbuf16.
// ---------------------------------------------------------------------------
__global__ __launch_bounds__(NTHR, 1)
void k_mlp2() {
    extern __shared__ __align__(16) __half smem[];
    __half* As = smem;                 // 4 stages of 128 rows
    __half* Bs = smem + 4 * TSTH;      // 4 stages of 256 rows

    const int e    = blockIdx.z;
    const int cnt  = g_cnt[e];
    const int row0 = blockIdx.y * BM;
    if (row0 >= cnt) return;
    const int col0 = blockIdx.x * BN2;

    const int tid  = threadIdx.x;
    const int lane = tid & 31;
    const int warp = tid >> 5;
    const int wm   = warp >> 2;
    const int wn   = warp & 3;
    const int grp  = lane >> 2;
    const int tig  = lane & 3;

    const int lrow = tid >> 1;
    const int lseg = (tid & 1) * 16;

    const __half* ap = g_act16 + (size_t)(e * CAP + row0 + lrow) * NDIM + lseg;
    const size_t wbo = (size_t)e * ((size_t)NDIM * KDIM);
    const __half* bp0 = g_wd16 + wbo + (size_t)(col0 + lrow) * NDIM + lseg;
    const __half* bp1 = g_wd16 + wbo + (size_t)(col0 + lrow + 128) * NDIM + lseg;

    const uint32_t sA = (uint32_t)__cvta_generic_to_shared(As);
    const uint32_t sB = (uint32_t)__cvta_generic_to_shared(Bs);
    const int alm = lane & 15, alh = lane >> 4;
    const int blm = lane & 7,  blh = (lane >> 3) & 1;
    const uint32_t aBase = sA + (uint32_t)((wm * 64 + alm) * SPADH + alh * 8) * 2;
    const uint32_t bBase = sB + (uint32_t)((wn * 64 + blm) * SPADH + blh * 8) * 2;

    const uint32_t wofA = (uint32_t)(lrow * SPADH + lseg) * 2;
    const uint32_t wofB0 = wofA;
    const uint32_t wofB1 = (uint32_t)((lrow + 128) * SPADH + lseg) * 2;

    float4 acc[4][8];
#pragma unroll
    for (int i = 0; i < 4; ++i)
#pragma unroll
        for (int j = 0; j < 8; ++j) acc[i][j] = make_float4(0.f, 0.f, 0.f, 0.f);

#define MLP2_CP(st, ko)                                                      \
    do {                                                                     \
        const uint32_t sa = sA + (uint32_t)(st) * (TSTH * 2);                \
        const uint32_t sb = sB + (uint32_t)(st) * (2 * TSTH * 2);            \
        cp16(sa + wofA,       ap  + (ko),     16);                           \
        cp16(sa + wofA + 16,  ap  + (ko) + 8, 16);                           \
        cp16(sb + wofB0,      bp0 + (ko),     16);                           \
        cp16(sb + wofB0 + 16, bp0 + (ko) + 8, 16);                           \
        cp16(sb + wofB1,      bp1 + (ko),     16);                           \
        cp16(sb + wofB1 + 16, bp1 + (ko) + 8, 16);                           \
    } while (0)

    const int KT = NDIM / BKT;   // 44
    MLP2_CP(0, 0);     CP_COMMIT();
    MLP2_CP(1, BKT);   CP_COMMIT();

#pragma unroll 1
    for (int kt = 0; kt < KT; ++kt) {
        if (kt + 2 < KT) MLP2_CP((kt + 2) & 3, (kt + 2) * BKT);
        CP_COMMIT();
        CP_WAIT2();
        __syncthreads();

        const int stC = kt & 3;
        const uint32_t aS = aBase + (uint32_t)stC * (TSTH * 2);
        const uint32_t bS = bBase + (uint32_t)stC * (2 * TSTH * 2);
#pragma unroll
        for (int ks = 0; ks < BKT; ks += 16) {
            uint32_t af[4][4], bf[8][2];
#pragma unroll
            for (int mt = 0; mt < 4; ++mt)
                ldsm_x4(af[mt], aS + (uint32_t)(mt * 16 * SPADH + ks) * 2);
#pragma unroll
            for (int nt = 0; nt < 8; ++nt)
                ldsm_x2(bf[nt], bS + (uint32_t)(nt * 8 * SPADH + ks) * 2);
#pragma unroll
            for (int mt = 0; mt < 4; ++mt)
#pragma unroll
                for (int nt = 0; nt < 8; ++nt)
                    mma16(acc[mt][nt], af[mt], bf[nt]);
        }
    }
#undef MLP2_CP

#pragma unroll
    for (int mt = 0; mt < 4; ++mt) {
        const int r0 = row0 + wm * 64 + mt * 16 + grp;
        const int r1 = r0 + 8;
#pragma unroll
        for (int nt = 0; nt < 8; ++nt) {
            const int c = col0 + wn * 64 + nt * 8 + tig * 2;
            float4 v = acc[mt][nt];
            if (r0 < cnt)
                *(__half2*)&g_dbuf16[(size_t)(e * CAP + r0) * KDIM + c] =
                    __floats2half2_rn(v.x, v.y);
            if (r1 < cnt)
                *(__half2*)&g_dbuf16[(size_t)(e * CAP + r1) * KDIM + c] =
                    __floats2half2_rn(v.z, v.w);
        }
    }
}

// ---------------- combine (fp16 d rows -> f32 out) ----------------
__global__ void k_combine(const float* __restrict__ gate, float* __restrict__ out) {
    const int t = blockIdx.x;
    const int p0 = g_posmap[2 * t];
    const int p1 = g_posmap[2 * t + 1];
    const float g0 = gate[2 * t];
    const float g1 = gate[2 * t + 1];
    const uint4* d0 = (const uint4*)(g_dbuf16 + (size_t)p0 * KDIM);
    const uint4* d1 = (const uint4*)(g_dbuf16 + (size_t)p1 * KDIM);
    float4* o = (float4*)(out + (size_t)t * KDIM);
    for (int i = threadIdx.x; i < KDIM / 8; i += blockDim.x) {
        uint4 a = d0[i];
        uint4 b = d1[i];
        const __half2* ah = (const __half2*)&a;
        const __half2* bh = (const __half2*)&b;
        float4 o0, o1;
        float2 a0 = __half22float2(ah[0]), b0 = __half22float2(bh[0]);
        float2 a1 = __half22float2(ah[1]), b1 = __half22float2(bh[1]);
        float2 a2 = __half22float2(ah[2]), b2 = __half22float2(bh[2]);
        float2 a3 = __half22float2(ah[3]), b3 = __half22float2(bh[3]);
        o0.x = g0 * a0.x + g1 * b0.x;  o0.y = g0 * a0.y + g1 * b0.y;
        o0.z = g0 * a1.x + g1 * b1.x;  o0.w = g0 * a1.y + g1 * b1.y;
        o1.x = g0 * a2.x + g1 * b2.x;  o1.y = g0 * a2.y + g1 * b2.y;
        o1.z = g0 * a3.x + g1 * b3.x;  o1.w = g0 * a3.y + g1 * b3.y;
        o[i * 2]     = o0;
        o[i * 2 + 1] = o1;
    }
}

extern "C" void kernel_launch(void* const* d_in, const int* in_sizes, int n_in,
                              void* d_out, int out_size) {
    (void)in_sizes; (void)n_in; (void)out_size;
    const float* flat_h    = (const float*)d_in[0];
    const int*   flat_idx  = (const int*)  d_in[1];
    const float* flat_gate = (const float*)d_in[2];
    const float* gate_w    = (const float*)d_in[3];
    const float* up_w      = (const float*)d_in[4];
    const float* down_w    = (const float*)d_in[5];
    float* out = (float*)d_out;

    cudaFuncSetAttribute(k_mlp1, cudaFuncAttributeMaxDynamicSharedMemorySize, SMEM_BYTES);
    cudaFuncSetAttribute(k_mlp2, cudaFuncAttributeMaxDynamicSharedMemorySize, SMEM_BYTES);

    __half* d_h16;  cudaGetSymbolAddress((void**)&d_h16,  g_h16);
    __half* d_wg16; cudaGetSymbolAddress((void**)&d_wg16, g_wg16);
    __half* d_wu16; cudaGetSymbolAddress((void**)&d_wu16, g_wu16);
    __half* d_wd16; cudaGetSymbolAddress((void**)&d_wd16, g_wd16);

    const int HN = MTOK * KDIM;         // 4,194,304
    const int WN = (int)WELEMS;         // 23,068,672
    k_cvt<<<HN / 4096, 256>>>(flat_h, d_h16, HN);
    k_cvt<<<WN / 4096, 256>>>(gate_w, d_wg16, WN);
    k_cvt<<<WN / 4096, 256>>>(up_w,   d_wu16, WN);
    k_cvt<<<WN / 4096, 256>>>(down_w, d_wd16, WN);

    k_route<<<1, 256>>>(flat_idx);

    dim3 grid1(NDIM / BN1, CAP / BM, NEXP);   // (11, 8, 8)
    k_mlp1<<<grid1, NTHR, SMEM_BYTES>>>();

    dim3 grid2(KDIM / BN2, CAP / BM, NEXP);   // (8, 8, 8)
    k_mlp2<<<grid2, NTHR, SMEM_BYTES>>>();

    k_combine<<<MTOK, 256>>>(flat_gate, out);
}